// round 17
// baseline (speedup 1.0000x reference)
#include <cuda_runtime.h>
#include <cuda_fp16.h>
#include <math.h>
#include <stdint.h>

// Problem constants
#define TT 4096   // tokens = B*S
#define EE 64     // experts
#define KK 8      // top_k
#define HH 1024   // hidden
#define FF 512    // expert ffn
#define CC 1024   // capacity

// -------- scratch (__device__ globals; no allocation allowed) --------
__device__ int   g_expert_index[TT * KK];
__device__ float g_weights[TT * KK];
__device__ int   g_pair_pos[TT * KK];
__device__ int   g_row_token[EE * CC];
__device__ int   g_count[EE];
__device__ alignas(16) __half g_xh[(size_t)TT * HH];         // 8 MB  (x in half)
__device__ alignas(16) __half g_hbuf[(size_t)EE * CC * FF];  // 67 MB (half)
__device__ alignas(16) __half g_obuf[(size_t)EE * CC * HH];  // 134 MB (half)

// -------- helpers --------
__device__ __forceinline__ uint32_t smem_to_u32(const void* p) {
    uint32_t a;
    asm("{ .reg .u64 t; cvta.to.shared.u64 t, %1; cvt.u32.u64 %0, t; }"
        : "=r"(a) : "l"(p));
    return a;
}
__device__ __forceinline__ uint2 f4_to_h4(float4 v) {
    __half2 a = __floats2half2_rn(v.x, v.y);
    __half2 b = __floats2half2_rn(v.z, v.w);
    uint2 r;
    r.x = *reinterpret_cast<uint32_t*>(&a);
    r.y = *reinterpret_cast<uint32_t*>(&b);
    return r;
}
__device__ __forceinline__ uint4 f8_to_h8(float4 v0, float4 v1) {
    uint2 a = f4_to_h4(v0);
    uint2 b = f4_to_h4(v1);
    return make_uint4(a.x, a.y, b.x, b.y);
}
__device__ __forceinline__ void ldm_x4(uint32_t* r, uint32_t addr) {
    asm volatile("ldmatrix.sync.aligned.m8n8.x4.shared.b16 {%0,%1,%2,%3}, [%4];"
        : "=r"(r[0]), "=r"(r[1]), "=r"(r[2]), "=r"(r[3]) : "r"(addr));
}
__device__ __forceinline__ void ldm_x4t(uint32_t* r, uint32_t addr) {
    asm volatile("ldmatrix.sync.aligned.m8n8.x4.trans.shared.b16 {%0,%1,%2,%3}, [%4];"
        : "=r"(r[0]), "=r"(r[1]), "=r"(r[2]), "=r"(r[3]) : "r"(addr));
}
__device__ __forceinline__ void mma_f16(float* c, const uint32_t* a, const uint32_t* b) {
    asm volatile(
        "mma.sync.aligned.m16n8k16.row.col.f32.f16.f16.f32 "
        "{%0,%1,%2,%3},{%4,%5,%6,%7},{%8,%9},{%0,%1,%2,%3};"
        : "+f"(c[0]), "+f"(c[1]), "+f"(c[2]), "+f"(c[3])
        : "r"(a[0]), "r"(a[1]), "r"(a[2]), "r"(a[3]), "r"(b[0]), "r"(b[1]));
}
__device__ __forceinline__ void cp_async16(uint32_t dst, const void* src) {
    asm volatile("cp.async.cg.shared.global [%0], [%1], 16;" :: "r"(dst), "l"(src));
}
#define CP_COMMIT() asm volatile("cp.async.commit_group;" ::: "memory")
#define CP_WAIT0()  asm volatile("cp.async.wait_group 0;" ::: "memory")
#define CP_WAIT1()  asm volatile("cp.async.wait_group 1;" ::: "memory")

// ====================================================================
// Kernel 1: router — 16 tokens/block (2 per warp), w_router tiled.
// Also converts x -> g_xh (half) on the fly.
// ====================================================================
__global__ void __launch_bounds__(256) router_kernel(
    const float* __restrict__ x,
    const float* __restrict__ w_router,
    const float* __restrict__ bias,
    float* __restrict__ logits_out,
    float* __restrict__ idx_out)
{
    __shared__ float swT[128][65];
    __shared__ float sx[16][128];
    __shared__ float ssel[16][64];

    const int tid  = threadIdx.x;
    const int warp = tid >> 5;
    const int lane = tid & 31;
    const int t0   = blockIdx.x * 16;

    float acc0a = 0.f, acc1a = 0.f;
    float acc0b = 0.f, acc1b = 0.f;

    for (int hc = 0; hc < HH / 128; ++hc) {
        {
            const int e  = tid >> 2;
            const float* wr = w_router + (size_t)e * HH + hc * 128;
            #pragma unroll
            for (int p = 0; p < 8; ++p) {
                int h4 = (tid & 3) + p * 4;
                float4 v = *reinterpret_cast<const float4*>(wr + h4 * 4);
                swT[h4 * 4 + 0][e] = v.x;
                swT[h4 * 4 + 1][e] = v.y;
                swT[h4 * 4 + 2][e] = v.z;
                swT[h4 * 4 + 3][e] = v.w;
            }
        }
        {
            const int r  = tid >> 4;
            const int c4 = tid & 15;
            #pragma unroll
            for (int p = 0; p < 2; ++p) {
                int col4 = c4 + p * 16;
                size_t gidx = (size_t)(t0 + r) * HH + hc * 128 + col4 * 4;
                float4 v = *reinterpret_cast<const float4*>(x + gidx);
                *reinterpret_cast<float4*>(&sx[r][col4 * 4]) = v;
                *reinterpret_cast<uint2*>(g_xh + gidx) = f4_to_h4(v);
            }
        }
        __syncthreads();

        const float* sxa = sx[warp * 2];
        const float* sxb = sx[warp * 2 + 1];
        #pragma unroll 4
        for (int h = 0; h < 128; ++h) {
            float w0 = swT[h][lane];
            float w1 = swT[h][lane + 32];
            float xa = sxa[h];
            float xb = sxb[h];
            acc0a += xa * w0; acc1a += xa * w1;
            acc0b += xb * w0; acc1b += xb * w1;
        }
        __syncthreads();
    }

    #pragma unroll
    for (int tt = 0; tt < 2; ++tt) {
        const int t = t0 + warp * 2 + tt;
        const int srow = warp * 2 + tt;
        float acc0 = tt ? acc0b : acc0a;
        float acc1 = tt ? acc1b : acc1a;

        if (logits_out) {
            logits_out[(size_t)t * EE + lane]      = acc0;
            logits_out[(size_t)t * EE + lane + 32] = acc1;
        }

        float a0 = 1.0f / (1.0f + expf(-acc0));
        float a1 = 1.0f / (1.0f + expf(-acc1));
        ssel[srow][lane]      = a0 + bias[lane];
        ssel[srow][lane + 32] = a1 + bias[lane + 32];
        __syncwarp();

        int   sel_idx[KK];
        float sel_val[KK];
        #pragma unroll
        for (int k = 0; k < KK; ++k) {
            float v  = ssel[srow][lane];      int id = lane;
            float v2 = ssel[srow][lane + 32];
            if (v2 > v) { v = v2; id = lane + 32; }
            #pragma unroll
            for (int o = 16; o; o >>= 1) {
                float ov = __shfl_xor_sync(0xffffffffu, v, o);
                int   oi = __shfl_xor_sync(0xffffffffu, id, o);
                if (ov > v || (ov == v && oi < id)) { v = ov; id = oi; }
            }
            sel_idx[k] = id;
            sel_val[k] = v;
            if (lane == 0) ssel[srow][id] = -INFINITY;
            __syncwarp();
        }

        if (lane == 0) {
            float wsum = 0.f;
            float wv[KK];
            #pragma unroll
            for (int k = 0; k < KK; ++k) {
                wv[k] = sel_val[k] - bias[sel_idx[k]];
                wsum += wv[k];
            }
            #pragma unroll
            for (int k = 0; k < KK; ++k) {
                g_expert_index[t * KK + k] = sel_idx[k];
                g_weights[t * KK + k]      = wv[k] / wsum;
                if (idx_out) idx_out[(size_t)t * KK + k] = (float)sel_idx[k];
            }
        }
    }
}

// ====================================================================
// Kernel 2: slot assignment (exact order of flattened [t,k])
// ====================================================================
__global__ void pos_kernel()
{
    int e    = blockIdx.x;
    int tid  = threadIdx.x;
    int wid  = tid >> 5;
    int lane = tid & 31;
    const int NP    = TT * KK;
    const int chunk = NP / 256;
    __shared__ int wsum[8];

    int base = tid * chunk;
    int c = 0;
    for (int j = 0; j < chunk; ++j)
        if (g_expert_index[base + j] == e) c++;

    int v = c;
    #pragma unroll
    for (int o = 1; o < 32; o <<= 1) {
        int n = __shfl_up_sync(0xffffffffu, v, o);
        if (lane >= o) v += n;
    }
    if (lane == 31) wsum[wid] = v;
    __syncthreads();
    if (wid == 0 && lane < 8) {
        int s = wsum[lane];
        #pragma unroll
        for (int o = 1; o < 8; o <<= 1) {
            int n = __shfl_up_sync(0xffu, s, o);
            if (lane >= o) s += n;
        }
        wsum[lane] = s;
    }
    __syncthreads();

    int off = v - c + (wid ? wsum[wid - 1] : 0);
    if (tid == 255) g_count[e] = off + c;

    for (int j = 0; j < chunk; ++j) {
        int i = base + j;
        if (g_expert_index[i] == e) {
            g_pair_pos[i] = off;
            if (off < CC) g_row_token[e * CC + off] = i / KK;
            off++;
        }
    }
}

// ====================================================================
// Kernel 3: gate+up GEMM + SiLU*u -> hbuf(half)
// 128 threads, 4 warps 2m x 2n, warp tile 64m x 32n per output (64x64 total).
// CTA: M=128, N=64.  BK=32.  3-stage A pipe, 2-stage B.
// Dyn SMEM: A 3x10240 @0; Bg 2x4608 @30720; Bu 2x4608 @39936. 49152.
// grid = (CC/128=8 [m fastest], FF/64=8, EE)
// ====================================================================
__global__ void __launch_bounds__(128, 2) gemm1_mma(const float* __restrict__ w_gate,
                                                    const float* __restrict__ w_up)
{
    const int e  = blockIdx.z;
    const int m0 = blockIdx.x * 128;
    const int n0 = blockIdx.y * 64;

    int cnt = g_count[e];
    cnt = (cnt < CC) ? cnt : CC;
    if (m0 >= cnt) return;

    extern __shared__ unsigned char sbuf[];
    __shared__ int stok[128];

    const int tid  = threadIdx.x;
    const int wid  = tid >> 5;
    const int lane = tid & 31;
    const int wm   = wid >> 1;      // 0..1 (64 rows each)
    const int wn   = wid & 1;       // 0..1 (32 cols each)

    {
        int slot = m0 + tid;
        if (slot >= cnt) slot = cnt - 1;
        stok[tid] = g_row_token[e * CC + slot];
    }
    __syncthreads();

    const uint32_t sA = smem_to_u32(sbuf);

    // A: one row per thread (64B), 4 cp16
    const __half* xrow = g_xh + (size_t)stok[tid] * HH;
    const uint32_t a_off = tid * 80;
    // B: b_krow = tid>>2 (0..31), 16 floats at col (tid&3)*16
    const int b_krow = tid >> 2;
    const int b_col  = (tid & 3) * 16;
    const float* wg_src = w_gate + (size_t)e * HH * FF + n0 + (size_t)b_krow * FF + b_col;
    const float* wu_src = w_up   + (size_t)e * HH * FF + n0 + (size_t)b_krow * FF + b_col;
    const int b_soff = b_krow * 144 + b_col * 2;   // halves -> bytes: col*2

    const int fa_row  = (lane & 7) + ((lane >> 3) & 1) * 8;
    const int fa_koff = (lane >> 4) * 16;
    const int fb_k    = (lane & 7) + ((lane >> 3) & 1) * 8;
    const int fb_noff = (wn * 32 + (lane >> 4) * 8) * 2;

    float accg[4][4][4];
    float accu[4][4][4];
    #pragma unroll
    for (int mi = 0; mi < 4; ++mi)
        #pragma unroll
        for (int nj = 0; nj < 4; ++nj)
            #pragma unroll
            for (int qq = 0; qq < 4; ++qq) { accg[mi][nj][qq] = 0.f; accu[mi][nj][qq] = 0.f; }

    uint4 bgp[2], bup[2];

    // prologue: A chunks 0,1 in flight; B chunk 0 in smem
    {
        #pragma unroll
        for (int q = 0; q < 4; ++q)
            cp_async16(sA + a_off + q * 16, xrow + q * 8);
        CP_COMMIT();
        #pragma unroll
        for (int q = 0; q < 4; ++q)
            cp_async16(sA + 10240 + a_off + q * 16, xrow + 32 + q * 8);
        CP_COMMIT();
        float4 g0 = *reinterpret_cast<const float4*>(wg_src + 0);
        float4 g1 = *reinterpret_cast<const float4*>(wg_src + 4);
        float4 g2 = *reinterpret_cast<const float4*>(wg_src + 8);
        float4 g3 = *reinterpret_cast<const float4*>(wg_src + 12);
        float4 u0 = *reinterpret_cast<const float4*>(wu_src + 0);
        float4 u1 = *reinterpret_cast<const float4*>(wu_src + 4);
        float4 u2 = *reinterpret_cast<const float4*>(wu_src + 8);
        float4 u3 = *reinterpret_cast<const float4*>(wu_src + 12);
        *reinterpret_cast<uint4*>(sbuf + 30720 + b_soff +  0) = f8_to_h8(g0, g1);
        *reinterpret_cast<uint4*>(sbuf + 30720 + b_soff + 16) = f8_to_h8(g2, g3);
        *reinterpret_cast<uint4*>(sbuf + 39936 + b_soff +  0) = f8_to_h8(u0, u1);
        *reinterpret_cast<uint4*>(sbuf + 39936 + b_soff + 16) = f8_to_h8(u2, u3);
    }
    CP_WAIT1();
    __syncthreads();

    const int NK = HH / 32;   // 32
    int abuf = 0;
    for (int kc = 0; kc < NK; ++kc) {
        const int cur = kc & 1;
        if (kc + 2 < NK) {
            const int k0 = (kc + 2) * 32;
            int nb = abuf + 2; if (nb >= 3) nb -= 3;
            const uint32_t Ad = sA + nb * 10240 + a_off;
            #pragma unroll
            for (int q = 0; q < 4; ++q)
                cp_async16(Ad + q * 16, xrow + k0 + q * 8);
        }
        CP_COMMIT();
        if (kc + 1 < NK) {
            const size_t koff = (size_t)(kc + 1) * 32 * FF;
            float4 g0 = *reinterpret_cast<const float4*>(wg_src + koff + 0);
            float4 g1 = *reinterpret_cast<const float4*>(wg_src + koff + 4);
            bgp[0] = f8_to_h8(g0, g1);
            float4 g2 = *reinterpret_cast<const float4*>(wg_src + koff + 8);
            float4 g3 = *reinterpret_cast<const float4*>(wg_src + koff + 12);
            bgp[1] = f8_to_h8(g2, g3);
            float4 u0 = *reinterpret_cast<const float4*>(wu_src + koff + 0);
            float4 u1 = *reinterpret_cast<const float4*>(wu_src + koff + 4);
            bup[0] = f8_to_h8(u0, u1);
            float4 u2 = *reinterpret_cast<const float4*>(wu_src + koff + 8);
            float4 u3 = *reinterpret_cast<const float4*>(wu_src + koff + 12);
            bup[1] = f8_to_h8(u2, u3);
        }

        const uint32_t Ab  = sA + abuf * 10240;
        const uint32_t Bgb = sA + 30720 + cur * 4608;
        const uint32_t Bub = sA + 39936 + cur * 4608;
        #pragma unroll
        for (int ks = 0; ks < 2; ++ks) {
            uint32_t a[4][4];
            #pragma unroll
            for (int mi = 0; mi < 4; ++mi)
                ldm_x4(a[mi], Ab + (wm * 64 + mi * 16 + fa_row) * 80 + ks * 32 + fa_koff);
            #pragma unroll
            for (int pf = 0; pf < 2; ++pf) {
                uint32_t bg[4], bu[4];
                int boff = (ks * 16 + fb_k) * 144 + fb_noff + pf * 32;
                ldm_x4t(bg, Bgb + boff);
                ldm_x4t(bu, Bub + boff);
                #pragma unroll
                for (int mi = 0; mi < 4; ++mi) {
                    mma_f16(accg[mi][pf * 2 + 0], a[mi], bg + 0);
                    mma_f16(accg[mi][pf * 2 + 1], a[mi], bg + 2);
                    mma_f16(accu[mi][pf * 2 + 0], a[mi], bu + 0);
                    mma_f16(accu[mi][pf * 2 + 1], a[mi], bu + 2);
                }
            }
        }

        if (kc + 1 < NK) {
            unsigned char* nbg = sbuf + 30720 + (cur ^ 1) * 4608;
            unsigned char* nbu = sbuf + 39936 + (cur ^ 1) * 4608;
            *reinterpret_cast<uint4*>(nbg + b_soff +  0) = bgp[0];
            *reinterpret_cast<uint4*>(nbg + b_soff + 16) = bgp[1];
            *reinterpret_cast<uint4*>(nbu + b_soff +  0) = bup[0];
            *reinterpret_cast<uint4*>(nbu + b_soff + 16) = bup[1];
        }
        CP_WAIT1();
        __syncthreads();
        if (++abuf == 3) abuf = 0;
    }

    // epilogue: h = silu(g) * u -> half
    const int frow = lane >> 2;
    const int fcol = (lane & 3) * 2;
    #pragma unroll
    for (int mi = 0; mi < 4; ++mi) {
        #pragma unroll
        for (int nj = 0; nj < 4; ++nj) {
            int m = m0 + wm * 64 + mi * 16 + frow;
            int n = n0 + wn * 32 + nj * 8 + fcol;
            #pragma unroll
            for (int half = 0; half < 2; ++half) {
                float g0 = accg[mi][nj][half * 2 + 0];
                float g1 = accg[mi][nj][half * 2 + 1];
                float u0 = accu[mi][nj][half * 2 + 0];
                float u1 = accu[mi][nj][half * 2 + 1];
                float h0 = (g0 / (1.0f + expf(-g0))) * u0;
                float h1 = (g1 / (1.0f + expf(-g1))) * u1;
                *reinterpret_cast<__half2*>(
                    &g_hbuf[((size_t)e * CC + m + half * 8) * FF + n]) =
                    __floats2half2_rn(h0, h1);
            }
        }
    }
}

// ====================================================================
// Kernel 4: down GEMM: hbuf(half) x w_down -> obuf(half)
// 128 threads, 4 warps 2m x 2n, warp tile 64m x 64n.
// CTA: M=128, N=128.  BK=32, 2-stage double buffer.
// Static SMEM: A0=0(10240) A1=10240, B0=20480(8704) B1=29184; 37888.
// grid = (CC/128=8 [m fastest], HH/128=8, EE)
// ====================================================================
__global__ void __launch_bounds__(128, 2) gemm2_mma(const float* __restrict__ w_down)
{
    const int e  = blockIdx.z;
    const int m0 = blockIdx.x * 128;
    const int n0 = blockIdx.y * 128;

    int cnt = g_count[e];
    cnt = (cnt < CC) ? cnt : CC;
    if (m0 >= cnt) return;

    __shared__ alignas(16) unsigned char sbuf[37888];

    const int tid  = threadIdx.x;
    const int wid  = tid >> 5;
    const int lane = tid & 31;
    const int wm   = wid >> 1;
    const int wn   = wid & 1;

    const uint32_t sA = smem_to_u32(sbuf);

    // A: one row per thread, 4 cp16
    const __half* a_src = g_hbuf + ((size_t)e * CC + m0 + tid) * FF;
    const uint32_t a_off = tid * 80;
    // B: b_krow = tid>>2 (0..31), 32 floats at col (tid&3)*32
    const int b_krow = tid >> 2;
    const int b_col  = (tid & 3) * 32;
    const float* b_src = w_down + (size_t)e * FF * HH + n0 + (size_t)b_krow * HH + b_col;
    const int b_soff = b_krow * 272 + b_col * 2;

    const int fa_row  = (lane & 7) + ((lane >> 3) & 1) * 8;
    const int fa_koff = (lane >> 4) * 16;
    const int fb_k    = (lane & 7) + ((lane >> 3) & 1) * 8;
    const int fb_noff = (wn * 64 + (lane >> 4) * 8) * 2;

    float acc[4][8][4];
    #pragma unroll
    for (int mi = 0; mi < 4; ++mi)
        #pragma unroll
        for (int nj = 0; nj < 8; ++nj)
            #pragma unroll
            for (int qq = 0; qq < 4; ++qq) acc[mi][nj][qq] = 0.f;

    uint4 bp[4];

    // prologue chunk 0
    {
        #pragma unroll
        for (int q = 0; q < 4; ++q)
            cp_async16(sA + a_off + q * 16, a_src + q * 8);
        CP_COMMIT();
        #pragma unroll
        for (int s = 0; s < 4; ++s) {
            float4 v0 = *reinterpret_cast<const float4*>(b_src + s * 8 + 0);
            float4 v1 = *reinterpret_cast<const float4*>(b_src + s * 8 + 4);
            *reinterpret_cast<uint4*>(sbuf + 20480 + b_soff + s * 16) = f8_to_h8(v0, v1);
        }
    }
    CP_WAIT0();
    __syncthreads();

    const int NK = FF / 32;   // 16
    for (int kc = 0; kc < NK; ++kc) {
        const int cur = kc & 1;
        const int has_next = (kc + 1 < NK);
        if (has_next) {
            const int k0 = (kc + 1) * 32;
            const uint32_t Ad = sA + (cur ^ 1) * 10240 + a_off;
            #pragma unroll
            for (int q = 0; q < 4; ++q)
                cp_async16(Ad + q * 16, a_src + k0 + q * 8);
            CP_COMMIT();
            const float* bs = b_src + (size_t)k0 * HH;
            #pragma unroll
            for (int s = 0; s < 4; ++s) {
                float4 v0 = *reinterpret_cast<const float4*>(bs + s * 8 + 0);
                float4 v1 = *reinterpret_cast<const float4*>(bs + s * 8 + 4);
                bp[s] = f8_to_h8(v0, v1);
            }
        }

        const uint32_t Ab = sA + cur * 10240;
        const uint32_t Bb = sA + 20480 + cur * 8704;
        #pragma unroll
        for (int ks = 0; ks < 2; ++ks) {
            uint32_t a[4][4];
            #pragma unroll
            for (int mi = 0; mi < 4; ++mi)
                ldm_x4(a[mi], Ab + (wm * 64 + mi * 16 + fa_row) * 80 + ks * 32 + fa_koff);
            #pragma unroll
            for (int pf = 0; pf < 4; ++pf) {
                uint32_t b[4];
                ldm_x4t(b, Bb + (ks * 16 + fb_k) * 272 + fb_noff + pf * 32);
                #pragma unroll
                for (int mi = 0; mi < 4; ++mi) {
                    mma_f16(acc[mi][pf * 2 + 0], a[mi], b + 0);
                    mma_f16(acc[mi][pf * 2 + 1], a[mi], b + 2);
                }
            }
        }

        if (has_next) {
            unsigned char* nb = sbuf + 20480 + (cur ^ 1) * 8704;
            #pragma unroll
            for (int s = 0; s < 4; ++s)
                *reinterpret_cast<uint4*>(nb + b_soff + s * 16) = bp[s];
        }
        CP_WAIT0();
        __syncthreads();
    }

    const int frow = lane >> 2;
    const int fcol = (lane & 3) * 2;
    #pragma unroll
    for (int mi = 0; mi < 4; ++mi) {
        #pragma unroll
        for (int nj = 0; nj < 8; ++nj) {
            int m = m0 + wm * 64 + mi * 16 + frow;
            int n = n0 + wn * 64 + nj * 8 + fcol;
            #pragma unroll
            for (int half = 0; half < 2; ++half) {
                *reinterpret_cast<__half2*>(
                    &g_obuf[((size_t)e * CC + m + half * 8) * HH + n]) =
                    __floats2half2_rn(acc[mi][nj][half * 2 + 0],
                                      acc[mi][nj][half * 2 + 1]);
            }
        }
    }
}

// ====================================================================
// Kernel 5: combine — y[t] = sum_k w[t,k] * obuf[row(t,k)]
// ====================================================================
__global__ void __launch_bounds__(128) combine_kernel(float* __restrict__ y)
{
    int t = blockIdx.x;
    __shared__ int   srow[KK];
    __shared__ float sw[KK];
    if (threadIdx.x < KK) {
        int i = t * KK + threadIdx.x;
        int e = g_expert_index[i];
        int p = g_pair_pos[i];
        srow[threadIdx.x] = (p < CC) ? (e * CC + p) : -1;
        sw[threadIdx.x]   = g_weights[i];
    }
    __syncthreads();

    const int h0 = threadIdx.x * 8;
    float a[8];
    #pragma unroll
    for (int q = 0; q < 8; ++q) a[q] = 0.f;
    #pragma unroll
    for (int k = 0; k < KK; ++k) {
        int r = srow[k];
        if (r >= 0) {
            float wk = sw[k];
            uint4 v = *reinterpret_cast<const uint4*>(&g_obuf[(size_t)r * HH + h0]);
            const __half2* hp = reinterpret_cast<const __half2*>(&v);
            #pragma unroll
            for (int q = 0; q < 4; ++q) {
                float2 f = __half22float2(hp[q]);
                a[q * 2 + 0] += wk * f.x;
                a[q * 2 + 1] += wk * f.y;
            }
        }
    }
    float4* yp = reinterpret_cast<float4*>(&y[(size_t)t * HH + h0]);
    yp[0] = make_float4(a[0], a[1], a[2], a[3]);
    yp[1] = make_float4(a[4], a[5], a[6], a[7]);
}

// ====================================================================
extern "C" void kernel_launch(void* const* d_in, const int* in_sizes, int n_in,
                              void* d_out, int out_size)
{
    const float* x        = (const float*)d_in[0];
    const float* w_router = (const float*)d_in[1];
    const float* bias     = (const float*)d_in[2];
    const float* w_gate   = (const float*)d_in[3];
    const float* w_up     = (const float*)d_in[4];
    const float* w_down   = (const float*)d_in[5];

    float* y = (float*)d_out;
    float* logits_out = nullptr;
    float* idx_out    = nullptr;
    long long base = (long long)TT * HH;
    if ((long long)out_size >= base + (long long)TT * EE)
        logits_out = y + base;
    if ((long long)out_size >= base + (long long)TT * EE + (long long)TT * KK)
        idx_out = y + base + (long long)TT * EE;

    const int SMEM1 = 49152;
    cudaFuncSetAttribute(gemm1_mma, cudaFuncAttributeMaxDynamicSharedMemorySize, SMEM1);

    router_kernel<<<TT / 16, 256>>>(x, w_router, bias, logits_out, idx_out);
    pos_kernel<<<EE, 256>>>();
    gemm1_mma<<<dim3(CC / 128, FF / 64, EE), 128, SMEM1>>>(w_gate, w_up);
    gemm2_mma<<<dim3(CC / 128, HH / 128, EE), 128>>>(w_down);
    combine_kernel<<<TT, 128>>>(y);
}